// round 15
// baseline (speedup 1.0000x reference)
#include <cuda_runtime.h>

#define NQ    14
#define NS    16384
#define NTH   512
#define BATCH 512
#define GRID  152
#define PAD_SLOTS (NS + (NS >> 5))   // 16896

typedef unsigned long long u64;

// ---------------- INVERSE MCX permutation table (pre-padded) + counter ------
__device__ unsigned short d_permtab[NS];
__device__ int d_ctr;

__global__ void build_perm_kernel() {
    int i = blockIdx.x * blockDim.x + threadIdx.x;
    if (i == 0) d_ctr = 0;
    unsigned x = (unsigned)i;
#pragma unroll
    for (int w = NQ - 1; w >= 0; w--) {
        const int p1 = NQ - 1 - w;
        const int p2 = NQ - 1 - ((w + 1) % NQ);
        const int pt = NQ - 1 - ((w + 2) % NQ);
        unsigned b1 = (x >> p1) & 1u;
        unsigned b2 = (x >> p2) & 1u;
        x ^= ((b1 & (b2 ^ 1u)) << pt);
    }
    d_permtab[i] = (unsigned short)(x + (x >> 5));   // padded slot index
}

// ---------------- packed f32x2 primitives ------------------------------------
__device__ __forceinline__ u64 mul2(u64 a, u64 b) {
    u64 d; asm("mul.rn.f32x2 %0,%1,%2;" : "=l"(d) : "l"(a), "l"(b)); return d;
}
__device__ __forceinline__ u64 fma2(u64 a, u64 b, u64 c) {
    u64 d; asm("fma.rn.f32x2 %0,%1,%2,%3;" : "=l"(d) : "l"(a), "l"(b), "l"(c)); return d;
}
__device__ __forceinline__ u64 pk2(float lo, float hi) {
    u64 d; asm("mov.b64 %0,{%1,%2};" : "=l"(d) : "f"(lo), "f"(hi)); return d;
}
__device__ __forceinline__ void up2(u64 v, float& lo, float& hi) {
    asm("mov.b64 {%0,%1},%2;" : "=f"(lo), "=f"(hi) : "l"(v));
}
__device__ __forceinline__ u64 swp(u64 v) {
    float lo, hi; up2(v, lo, hi); return pk2(hi, lo);
}

struct Gf { u64 T, Tn; };
__device__ __forceinline__ Gf mkgf(float t) {
    Gf g; g.T = pk2(t, t); g.Tn = pk2(-t, -t); return g;
}

// scaled mix: x' = x - i t y ; y' = y - i t x
__device__ __forceinline__ void mix2f(u64& Xr, u64& Xi, u64& Yr, u64& Yi, const Gf& g) {
    u64 xr = Xr, xi = Xi, yr = Yr, yi = Yi;
    Xr = fma2(g.T,  yi, xr);
    Xi = fma2(g.Tn, yr, xi);
    Yr = fma2(g.T,  xi, yr);
    Yi = fma2(g.Tn, xr, yi);
}

template <int MA, int MB>
__device__ __forceinline__ void xxf(u64* Ar, u64* Ai, const Gf& g) {
    const int M = MA | MB;
#pragma unroll
    for (int t = 0; t < 16; t++) {
        if (t & M) continue;
        mix2f(Ar[t],      Ai[t],      Ar[t ^ M],  Ai[t ^ M],  g);
        mix2f(Ar[t | MA], Ai[t | MA], Ar[t | MB], Ai[t | MB], g);
    }
}
template <int M>
__device__ __forceinline__ void rxf(u64* Ar, u64* Ai, const Gf& g) {
#pragma unroll
    for (int t = 0; t < 16; t++) {
        if (t & M) continue;
        mix2f(Ar[t], Ai[t], Ar[t | M], Ai[t | M], g);
    }
}
template <int M>
__device__ __forceinline__ void rzf(u64* Ar, u64* Ai, const Gf& g) {
#pragma unroll
    for (int t = 0; t < 16; t++) {
        u64 r = Ar[t], i = Ai[t];
        if (t & M) {
            Ar[t] = fma2(g.Tn, i, r);
            Ai[t] = fma2(g.T,  r, i);
        } else {
            Ar[t] = fma2(g.T,  i, r);
            Ai[t] = fma2(g.Tn, r, i);
        }
    }
}
// XX between the PACK bit and reg bit MB (register half-swaps, no shuffles)
template <int MB>
__device__ __forceinline__ void xxpf(u64* Ar, u64* Ai, float tv) {
    u64 T = pk2(tv, tv), Tn = pk2(-tv, -tv);
#pragma unroll
    for (int t = 0; t < 16; t++) {
        if (t & MB) continue;
        const int u = t | MB;
        u64 sxr = swp(Ar[t]), sxi = swp(Ai[t]);
        u64 syr = swp(Ar[u]), syi = swp(Ai[u]);
        Ar[t] = fma2(T,  syi, Ar[t]);
        Ai[t] = fma2(Tn, syr, Ai[t]);
        Ar[u] = fma2(T,  sxi, Ar[u]);
        Ai[u] = fma2(Tn, sxr, Ai[u]);
    }
}
// Rz on the PACK bit (asymmetric constants; elementwise)
__device__ __forceinline__ void rzpf(u64* Ar, u64* Ai, float tv) {
    u64 Tm  = pk2(tv, -tv);
    u64 Tmn = pk2(-tv, tv);
#pragma unroll
    for (int t = 0; t < 16; t++) {
        u64 r = Ar[t], i = Ai[t];
        Ar[t] = fma2(Tm,  i, r);
        Ai[t] = fma2(Tmn, r, i);
    }
}
__device__ __forceinline__ void scale32(u64* Ar, u64* Ai, float k) {
    u64 K = pk2(k, k);
#pragma unroll
    for (int t = 0; t < 16; t++) { Ar[t] = mul2(K, Ar[t]); Ai[t] = mul2(K, Ai[t]); }
}

// (-i)^k rotation
__device__ __forceinline__ void rot_mi(int k, float r, float i, float& orr, float& oi) {
    switch (k & 3) {
        case 0:  orr = r;  oi = i;  break;
        case 1:  orr = i;  oi = -r; break;
        case 2:  orr = -r; oi = -i; break;
        default: orr = -i; oi = r;  break;
    }
}

// one component of  Rz(wa)Rz(wb) * XX(phi) * (Rx|0> (x) Rx|0>)  on a wire pair
__device__ void pair_component(const float* p, const float* cp, int b,
                               int wa, int wb, int xxidx, int sel,
                               float& outr, float& outi) {
    float ca, sa, cbw, sbw, cx, sx;
    sincosf(0.5f * p[b * 42 + wa], &sa, &ca);
    sincosf(0.5f * p[b * 42 + wb], &sbw, &cbw);
    sincosf(0.5f * cp[b * 14 + xxidx], &sx, &cx);
    float vr[4] = {ca * cbw, 0.0f, 0.0f, -sa * sbw};
    float vi[4] = {0.0f, -ca * sbw, -sa * cbw, 0.0f};
    float nr[4], ni[4];
    nr[0] = cx * vr[0] + sx * vi[3]; ni[0] = cx * vi[0] - sx * vr[3];
    nr[3] = cx * vr[3] + sx * vi[0]; ni[3] = cx * vi[3] - sx * vr[0];
    nr[1] = cx * vr[1] + sx * vi[2]; ni[1] = cx * vi[1] - sx * vr[2];
    nr[2] = cx * vr[2] + sx * vi[1]; ni[2] = cx * vi[2] - sx * vr[1];
    float tha = p[b * 42 + 14 + wa], thb = p[b * 42 + 14 + wb];
    float ph = 0.5f * (((sel >> 1) ? tha : -tha) + ((sel & 1) ? thb : -thb));
    float cph, sph; sincosf(ph, &sph, &cph);
    float ur = nr[sel], ui = ni[sel];
    outr = ur * cph - ui * sph;
    outi = ui * cph + ur * sph;
}

// ---------------- main kernel ------------------------------------------------
__global__ void __launch_bounds__(NTH, 1)
quantum_kernel(const float* __restrict__ cp, const float* __restrict__ p,
               float* __restrict__ out) {
    extern __shared__ float sm[];
    float* RE = sm;
    float* IM = sm + PAD_SLOTS;

    __shared__ float c1[NQ], s1[NQ];
    __shared__ float txv[NQ];          // tan(xx half): [0..6]=a, [7..13]=b
    __shared__ float t3[NQ];           // tan(rx3 half)
    __shared__ float tz[NQ];           // tan(rz half)
    __shared__ float Whr[16], Whi[16]; // wires 0-3 table (prefix + XXb(1,2), Rx3(1,2))
    __shared__ float chi_r[4], chi_i[4];
    __shared__ float kapA[3];
    __shared__ float red[16][11];
    __shared__ int sm_b;

    const int tid = threadIdx.x;

    // prologue: fetch first batch id
    if (tid == 0) sm_b = atomicAdd(&d_ctr, 1);
    __syncthreads();

    for (;;) {
        const int b = sm_b;
        if (b >= BATCH) break;

        // ================= setup (single stage, no serial section) ==========
        if (tid < 32) {
            // warp 0: Vh table (lanes 0-15), chi (16-19), then shuffle-fold
            float fvr = 0.0f, fvi = 0.0f;
            if (tid < 16) {
                float w1r, w1i, w2r, w2i;
                pair_component(p, cp, b, 0, 1, 0, tid >> 2, w1r, w1i);
                pair_component(p, cp, b, 2, 3, 1, tid & 3,  w2r, w2i);
                fvr = w1r * w2r - w1i * w2i;
                fvi = w1r * w2i + w1i * w2r;
            } else if (tid < 20) {
                float cr_, ci_;
                pair_component(p, cp, b, 12, 13, 6, tid - 16, cr_, ci_);
                chi_r[tid - 16] = cr_; chi_i[tid - 16] = ci_;
            }
            __syncwarp();
            // fold XXb(1,2), Rx3(1), Rx3(2) into W via warp shuffles (exact)
            float cx, sx, pr_, pi_, nr_, ni_;
            sincosf(0.5f * cp[b * NQ + 7], &sx, &cx);        // XXb(1,2): mask 6
            pr_ = __shfl_xor_sync(0xffffffffu, fvr, 6);
            pi_ = __shfl_xor_sync(0xffffffffu, fvi, 6);
            nr_ = cx * fvr + sx * pi_; ni_ = cx * fvi - sx * pr_;
            fvr = nr_; fvi = ni_;
            sincosf(0.5f * p[b * 42 + 28 + 1], &sx, &cx);    // Rx3(1): mask 4
            pr_ = __shfl_xor_sync(0xffffffffu, fvr, 4);
            pi_ = __shfl_xor_sync(0xffffffffu, fvi, 4);
            nr_ = cx * fvr + sx * pi_; ni_ = cx * fvi - sx * pr_;
            fvr = nr_; fvi = ni_;
            sincosf(0.5f * p[b * 42 + 28 + 2], &sx, &cx);    // Rx3(2): mask 2
            pr_ = __shfl_xor_sync(0xffffffffu, fvr, 2);
            pi_ = __shfl_xor_sync(0xffffffffu, fvi, 2);
            nr_ = cx * fvr + sx * pi_; ni_ = cx * fvi - sx * pr_;
            fvr = nr_; fvi = ni_;
            if (tid < 16) { Whr[tid] = fvr; Whi[tid] = fvi; }
        }
        else if (tid >= 32 && tid < 32 + NQ) {
            int w = tid - 32;
            float c, s; sincosf(0.5f * cp[b * NQ + w], &s, &c);
            txv[w] = __fdividef(s, c);
        }
        else if (tid >= 64 && tid < 64 + NQ) {
            int w = tid - 64;
            float c, s; sincosf(0.5f * p[b * 42 + 28 + w], &s, &c);
            t3[w] = __fdividef(s, c);
        }
        else if (tid >= 96 && tid < 96 + NQ) {
            int w = tid - 96;
            float c, s; sincosf(0.5f * p[b * 42 + 14 + w], &s, &c);
            tz[w] = __fdividef(s, c);
        }
        else if (tid >= 128 && tid < 128 + NQ) {
            int w = tid - 128;
            sincosf(0.5f * p[b * 42 + w], &s1[w], &c1[w]);
        }
        else if (tid == 160) {          // phase A deferred cosines
            float k = cosf(0.5f * cp[b * 14 + 2]) * cosf(0.5f * cp[b * 14 + 3])
                    * cosf(0.5f * cp[b * 14 + 8]) * cosf(0.5f * cp[b * 14 + 9]);
#pragma unroll
            for (int w = 4; w <= 7; w++) k *= cosf(0.5f * p[b * 42 + 14 + w]);
#pragma unroll
            for (int w = 3; w <= 6; w++) k *= cosf(0.5f * p[b * 42 + 28 + w]);
            kapA[0] = k;
        }
        else if (tid == 161) {          // phase B deferred cosines
            float k = cosf(0.5f * cp[b * 14 + 4])  * cosf(0.5f * cp[b * 14 + 5])
                    * cosf(0.5f * cp[b * 14 + 10]) * cosf(0.5f * cp[b * 14 + 11]);
#pragma unroll
            for (int w = 8; w <= 11; w++) k *= cosf(0.5f * p[b * 42 + 14 + w]);
#pragma unroll
            for (int w = 7; w <= 10; w++) k *= cosf(0.5f * p[b * 42 + 28 + w]);
            kapA[1] = k;
        }
        else if (tid == 162) {          // phase C deferred cosines
            float k = cosf(0.5f * cp[b * 14 + 12]) * cosf(0.5f * cp[b * 14 + 13])
                    * cosf(0.5f * p[b * 42 + 28 + 0])  * cosf(0.5f * p[b * 42 + 28 + 11])
                    * cosf(0.5f * p[b * 42 + 28 + 12]) * cosf(0.5f * p[b * 42 + 28 + 13]);
            kapA[2] = k;
        }
        __syncthreads();    // S1

        u64 Ar[16], Ai[16];

        // ====== PHASE A: resident wires {3,4,5,6,7} = j bits {10,9,8,7,6} ====
        // reg: t3=j10(w3) t2=j9(w4) t1=j8(w5) t0=j7(w6); pack=j6(w7)
        // thread: tid[8:6]=j[13:11] (wires 0,1,2); tid[5:0]=j[5:0] (wires 8-13)
        {
            float Pl = 1.0f;
            Pl *= ((tid >> 5) & 1) ? s1[8]  : c1[8];
            Pl *= ((tid >> 4) & 1) ? s1[9]  : c1[9];
            Pl *= ((tid >> 3) & 1) ? s1[10] : c1[10];
            Pl *= ((tid >> 2) & 1) ? s1[11] : c1[11];
            int pcl = __popc(tid & 0x3C);
            float Cr = chi_r[tid & 3], Ci = chi_i[tid & 3];
            float Br, Bi; rot_mi(pcl, Cr, Ci, Br, Bi);
            Br *= Pl; Bi *= Pl;
            int vb = ((tid >> 8) & 1) * 8 + ((tid >> 7) & 1) * 4 + ((tid >> 6) & 1) * 2;
            float X0r = Whr[vb]     * Br - Whi[vb]     * Bi;
            float X0i = Whr[vb]     * Bi + Whi[vb]     * Br;
            float X1r = Whr[vb | 1] * Br - Whi[vb | 1] * Bi;
            float X1i = Whr[vb | 1] * Bi + Whi[vb | 1] * Br;
            float c7 = c1[7], s7 = s1[7];
#pragma unroll
            for (int t = 0; t < 16; t++) {
                float f = 1.0f;
                f *= (t & 4) ? s1[4] : c1[4];
                f *= (t & 2) ? s1[5] : c1[5];
                f *= (t & 1) ? s1[6] : c1[6];
                float xr, xi;
                rot_mi(__popc(t & 7), (t & 8) ? X1r : X0r, (t & 8) ? X1i : X0i,
                       xr, xi);
                Ar[t] = pk2(xr * f * c7,  xi * f * s7);
                Ai[t] = pk2(xi * f * c7, -xr * f * s7);
            }
        }
        { Gf g = mkgf(txv[2]); xxf<4, 2>(Ar, Ai, g); }   // XXa(4,5)
        xxpf<1>(Ar, Ai, txv[3]);                         // XXa(6,7) pack x t0
        { Gf g = mkgf(tz[4]); rzf<4>(Ar, Ai, g); }
        { Gf g = mkgf(tz[5]); rzf<2>(Ar, Ai, g); }
        { Gf g = mkgf(tz[6]); rzf<1>(Ar, Ai, g); }
        rzpf(Ar, Ai, tz[7]);                             // Rz(7) on pack
        { Gf g = mkgf(txv[8]); xxf<8, 4>(Ar, Ai, g); }   // XXb(3,4)
        { Gf g = mkgf(txv[9]); xxf<2, 1>(Ar, Ai, g); }   // XXb(5,6)
        { Gf g = mkgf(t3[3]); rxf<8>(Ar, Ai, g); }
        { Gf g = mkgf(t3[4]); rxf<4>(Ar, Ai, g); }
        { Gf g = mkgf(t3[5]); rxf<2>(Ar, Ai, g); }
        { Gf g = mkgf(t3[6]); rxf<1>(Ar, Ai, g); }
        scale32(Ar, Ai, kapA[0]);
        {
            int a = ((tid >> 8) & 1) * 8448 + ((tid >> 7) & 1) * 4224
                  + ((tid >> 6) & 1) * 2112 + ((tid >> 5) & 1) * 33 + (tid & 31);
#pragma unroll
            for (int t = 0; t < 16; t++) {
                int o = a + ((t >> 3) & 1) * 1056 + ((t >> 2) & 1) * 528
                          + ((t >> 1) & 1) * 264  + (t & 1) * 132;
                float lo, hi;
                up2(Ar[t], lo, hi); RE[o] = lo; RE[o + 66] = hi;
                up2(Ai[t], lo, hi); IM[o] = lo; IM[o + 66] = hi;
            }
        }
        __syncthreads();    // S2

        // ====== PHASE B: resident wires {7,8,9,10,11} = j bits {6,5,4,3,2} ===
        {
            int a = (tid & 1) + ((tid >> 1) & 1) * 2 + ((tid >> 2) & 1) * 132
                  + ((tid >> 3) & 1) * 264 + ((tid >> 4) & 1) * 528
                  + ((tid >> 5) & 1) * 1056 + ((tid >> 6) & 1) * 2112
                  + ((tid >> 7) & 1) * 4224 + ((tid >> 8) & 1) * 8448;
#pragma unroll
            for (int t = 0; t < 16; t++) {
                int o = a + ((t >> 3) & 1) * 66 + ((t >> 2) & 1) * 33
                          + ((t >> 1) & 1) * 16 + (t & 1) * 8;
                Ar[t] = pk2(RE[o], RE[o + 4]);
                Ai[t] = pk2(IM[o], IM[o + 4]);
            }
            // prefetch next batch id (visibility via S3)
            if (tid == 0) sm_b = atomicAdd(&d_ctr, 1);

            { Gf g = mkgf(txv[4]); xxf<4, 2>(Ar, Ai, g); }   // XXa(8,9)
            xxpf<1>(Ar, Ai, txv[5]);                         // XXa(10,11) pack x t0
            { Gf g = mkgf(tz[8]);  rzf<4>(Ar, Ai, g); }
            { Gf g = mkgf(tz[9]);  rzf<2>(Ar, Ai, g); }
            { Gf g = mkgf(tz[10]); rzf<1>(Ar, Ai, g); }
            rzpf(Ar, Ai, tz[11]);                            // Rz(11) on pack
            { Gf g = mkgf(txv[10]); xxf<8, 4>(Ar, Ai, g); }  // XXb(7,8)
            { Gf g = mkgf(txv[11]); xxf<2, 1>(Ar, Ai, g); }  // XXb(9,10)
            { Gf g = mkgf(t3[7]);  rxf<8>(Ar, Ai, g); }
            { Gf g = mkgf(t3[8]);  rxf<4>(Ar, Ai, g); }
            { Gf g = mkgf(t3[9]);  rxf<2>(Ar, Ai, g); }
            { Gf g = mkgf(t3[10]); rxf<1>(Ar, Ai, g); }
            scale32(Ar, Ai, kapA[1]);
#pragma unroll
            for (int t = 0; t < 16; t++) {
                int o = a + ((t >> 3) & 1) * 66 + ((t >> 2) & 1) * 33
                          + ((t >> 1) & 1) * 16 + (t & 1) * 8;
                float lo, hi;
                up2(Ar[t], lo, hi); RE[o] = lo; RE[o + 4] = hi;
                up2(Ai[t], lo, hi); IM[o] = lo; IM[o + 4] = hi;
            }
        }
        __syncthreads();    // S3

        // ====== PHASE C: resident wires {0,11,12,13}+w10 = j {13,2,1,0}+j3 ===
        float k5;
        {
            k5 = kapA[2];   // stash before next iteration's setup overwrites
            int a = (tid & 1) * 16 + ((tid >> 1) & 1) * 33 + ((tid >> 2) & 1) * 66
                  + ((tid >> 3) & 1) * 132 + ((tid >> 4) & 1) * 264
                  + ((tid >> 5) & 1) * 528 + ((tid >> 6) & 1) * 1056
                  + ((tid >> 7) & 1) * 2112 + ((tid >> 8) & 1) * 4224;
#pragma unroll
            for (int t = 0; t < 16; t++) {
                int o = a + ((t >> 3) & 1) * 8448 + ((t >> 2) & 1) * 4
                          + ((t >> 1) & 1) * 2 + (t & 1);
                Ar[t] = pk2(RE[o], RE[o + 8]);
                Ai[t] = pk2(IM[o], IM[o + 8]);
            }
            { Gf g = mkgf(txv[12]); xxf<4, 2>(Ar, Ai, g); }  // XXb(11,12)
            { Gf g = mkgf(txv[13]); xxf<1, 8>(Ar, Ai, g); }  // XXb(13,0)
            { Gf g = mkgf(t3[0]);   rxf<8>(Ar, Ai, g); }
            { Gf g = mkgf(t3[11]);  rxf<4>(Ar, Ai, g); }
            { Gf g = mkgf(t3[12]);  rxf<2>(Ar, Ai, g); }
            { Gf g = mkgf(t3[13]);  rxf<1>(Ar, Ai, g); }

            // scaled probabilities -> smem (true prob = k5^2 * value)
#pragma unroll
            for (int t = 0; t < 16; t++) {
                int o = a + ((t >> 3) & 1) * 8448 + ((t >> 2) & 1) * 4
                          + ((t >> 1) & 1) * 2 + (t & 1);
                u64 Pr = fma2(Ai[t], Ai[t], mul2(Ar[t], Ar[t]));
                float lo, hi; up2(Pr, lo, hi);
                RE[o] = lo; RE[o + 8] = hi;
            }
        }
        __syncthreads();    // S4

        // ====== epilogue: inverse-permuted gather + Walsh trees ==============
        float l1[16], a4 = 0.0f;
#pragma unroll
        for (int k = 0; k < 16; k++) {
            int y0 = (k << 10) | tid;
            int y1 = y0 | 512;
            float v0 = RE[d_permtab[y0]];     // table stores padded slot
            float v1 = RE[d_permtab[y1]];
            l1[k] = v0 + v1;
            a4 += v0 - v1;
        }
        float l2[8], a3 = 0.0f;
#pragma unroll
        for (int k = 0; k < 8; k++) { l2[k] = l1[2*k] + l1[2*k+1]; a3 += l1[2*k] - l1[2*k+1]; }
        float l3[4], a2 = 0.0f;
#pragma unroll
        for (int k = 0; k < 4; k++) { l3[k] = l2[2*k] + l2[2*k+1]; a2 += l2[2*k] - l2[2*k+1]; }
        float l4[2], a1 = 0.0f;
#pragma unroll
        for (int k = 0; k < 2; k++) { l4[k] = l3[2*k] + l3[2*k+1]; a1 += l3[2*k] - l3[2*k+1]; }
        float T  = l4[0] + l4[1];
        float a0 = l4[0] - l4[1];

        // warp butterfly over lane bits 0..4 (tid bits <-> wires 13..9)
        float av[5] = {a0, a1, a2, a3, a4};
        float d[5];
#pragma unroll
        for (int k = 0; k < 5; k++) {
            float pT = __shfl_xor_sync(0xffffffffu, T, 1 << k);
            d[k] = T - pT;
            T += pT;
#pragma unroll
            for (int j = 0; j < 5; j++)
                av[j] += __shfl_xor_sync(0xffffffffu, av[j], 1 << k);
#pragma unroll
            for (int m = 0; m < 5; m++)
                if (m < k) d[m] += __shfl_xor_sync(0xffffffffu, d[m], 1 << k);
        }
        if ((tid & 31) == 0) {
            int wp = tid >> 5;
#pragma unroll
            for (int j = 0; j < 5; j++) red[wp][j] = av[j];
#pragma unroll
            for (int k = 0; k < 5; k++) red[wp][5 + k] = d[k];
            red[wp][10] = T;
        }
        __syncthreads();    // S5

        // parallel tail: warp w reduces wire w over the 16 partials
        if (tid < NQ * 32) {
            int w = tid >> 5;
            int r = tid & 31;
            float v = 0.0f;
            if (r < 16) {
                if (w < 5) {
                    v = red[r][w];                        // wires 0-4
                } else if (w < 9) {
                    float Tt = red[r][10];                // wires 5-8
                    v = ((r >> (8 - w)) & 1) ? -Tt : Tt;
                } else {
                    v = red[r][5 + (13 - w)];             // wires 9-13
                }
            }
#pragma unroll
            for (int o = 8; o; o >>= 1) v += __shfl_xor_sync(0xffffffffu, v, o);
            if (r == 0)
                out[b * NQ + w] = (v * k5) * k5;
        }
        // no loop-top barrier: next setup writes tables not read by the tail;
        // next RE writes happen only after S1.
    }
}

extern "C" void kernel_launch(void* const* d_in, const int* in_sizes, int n_in,
                              void* d_out, int out_size) {
    const float* cp = (const float*)d_in[0];   // (512, 14)
    const float* p  = (const float*)d_in[1];   // (512, 3, 14)
    float* out      = (float*)d_out;           // (512, 14)

    build_perm_kernel<<<NS / 1024, 1024>>>();

    size_t smem = (size_t)PAD_SLOTS * 2 * sizeof(float);  // 135168 bytes
    cudaFuncSetAttribute(quantum_kernel,
                         cudaFuncAttributeMaxDynamicSharedMemorySize, (int)smem);
    quantum_kernel<<<GRID, NTH, smem>>>(cp, p, out);
}

// round 16
// speedup vs baseline: 1.2476x; 1.2476x over previous
#include <cuda_runtime.h>

#define NQ    14
#define NS    16384
#define NTH   512
#define BATCH 512
#define GRID  152
#define PAD_SLOTS (NS + (NS >> 5))   // 16896

typedef unsigned long long u64;

// ---------------- INVERSE MCX permutation table (pre-padded) + counter ------
__device__ unsigned short d_permtab[NS];
__device__ int d_ctr;

__global__ void build_perm_kernel() {
    int i = blockIdx.x * blockDim.x + threadIdx.x;
    if (i == 0) d_ctr = 0;
    unsigned x = (unsigned)i;
#pragma unroll
    for (int w = NQ - 1; w >= 0; w--) {
        const int p1 = NQ - 1 - w;
        const int p2 = NQ - 1 - ((w + 1) % NQ);
        const int pt = NQ - 1 - ((w + 2) % NQ);
        unsigned b1 = (x >> p1) & 1u;
        unsigned b2 = (x >> p2) & 1u;
        x ^= ((b1 & (b2 ^ 1u)) << pt);
    }
    d_permtab[i] = (unsigned short)(x + (x >> 5));   // padded slot index
}

// ---------------- packed f32x2 primitives ------------------------------------
__device__ __forceinline__ u64 mul2(u64 a, u64 b) {
    u64 d; asm("mul.rn.f32x2 %0,%1,%2;" : "=l"(d) : "l"(a), "l"(b)); return d;
}
__device__ __forceinline__ u64 fma2(u64 a, u64 b, u64 c) {
    u64 d; asm("fma.rn.f32x2 %0,%1,%2,%3;" : "=l"(d) : "l"(a), "l"(b), "l"(c)); return d;
}
__device__ __forceinline__ u64 pk2(float lo, float hi) {
    u64 d; asm("mov.b64 %0,{%1,%2};" : "=l"(d) : "f"(lo), "f"(hi)); return d;
}
__device__ __forceinline__ void up2(u64 v, float& lo, float& hi) {
    asm("mov.b64 {%0,%1},%2;" : "=f"(lo), "=f"(hi) : "l"(v));
}
__device__ __forceinline__ u64 swp(u64 v) {
    float lo, hi; up2(v, lo, hi); return pk2(hi, lo);
}

struct Gf { u64 T, Tn; };
__device__ __forceinline__ Gf mkgf(float t) {
    Gf g; g.T = pk2(t, t); g.Tn = pk2(-t, -t); return g;
}

// scaled mix: x' = x - i t y ; y' = y - i t x
__device__ __forceinline__ void mix2f(u64& Xr, u64& Xi, u64& Yr, u64& Yi, const Gf& g) {
    u64 xr = Xr, xi = Xi, yr = Yr, yi = Yi;
    Xr = fma2(g.T,  yi, xr);
    Xi = fma2(g.Tn, yr, xi);
    Yr = fma2(g.T,  xi, yr);
    Yi = fma2(g.Tn, xr, yi);
}

template <int MA, int MB>
__device__ __forceinline__ void xxf(u64* Ar, u64* Ai, const Gf& g) {
    const int M = MA | MB;
#pragma unroll
    for (int t = 0; t < 16; t++) {
        if (t & M) continue;
        mix2f(Ar[t],      Ai[t],      Ar[t ^ M],  Ai[t ^ M],  g);
        mix2f(Ar[t | MA], Ai[t | MA], Ar[t | MB], Ai[t | MB], g);
    }
}
template <int M>
__device__ __forceinline__ void rxf(u64* Ar, u64* Ai, const Gf& g) {
#pragma unroll
    for (int t = 0; t < 16; t++) {
        if (t & M) continue;
        mix2f(Ar[t], Ai[t], Ar[t | M], Ai[t | M], g);
    }
}
template <int M>
__device__ __forceinline__ void rzf(u64* Ar, u64* Ai, const Gf& g) {
#pragma unroll
    for (int t = 0; t < 16; t++) {
        u64 r = Ar[t], i = Ai[t];
        if (t & M) {
            Ar[t] = fma2(g.Tn, i, r);
            Ai[t] = fma2(g.T,  r, i);
        } else {
            Ar[t] = fma2(g.T,  i, r);
            Ai[t] = fma2(g.Tn, r, i);
        }
    }
}
// XX between the PACK bit and reg bit MB (register half-swaps, no shuffles)
template <int MB>
__device__ __forceinline__ void xxpf(u64* Ar, u64* Ai, float tv) {
    u64 T = pk2(tv, tv), Tn = pk2(-tv, -tv);
#pragma unroll
    for (int t = 0; t < 16; t++) {
        if (t & MB) continue;
        const int u = t | MB;
        u64 sxr = swp(Ar[t]), sxi = swp(Ai[t]);
        u64 syr = swp(Ar[u]), syi = swp(Ai[u]);
        Ar[t] = fma2(T,  syi, Ar[t]);
        Ai[t] = fma2(Tn, syr, Ai[t]);
        Ar[u] = fma2(T,  sxi, Ar[u]);
        Ai[u] = fma2(Tn, sxr, Ai[u]);
    }
}
// Rz on the PACK bit (asymmetric constants; elementwise)
__device__ __forceinline__ void rzpf(u64* Ar, u64* Ai, float tv) {
    u64 Tm  = pk2(tv, -tv);
    u64 Tmn = pk2(-tv, tv);
#pragma unroll
    for (int t = 0; t < 16; t++) {
        u64 r = Ar[t], i = Ai[t];
        Ar[t] = fma2(Tm,  i, r);
        Ai[t] = fma2(Tmn, r, i);
    }
}
__device__ __forceinline__ void scale32(u64* Ar, u64* Ai, float k) {
    u64 K = pk2(k, k);
#pragma unroll
    for (int t = 0; t < 16; t++) { Ar[t] = mul2(K, Ar[t]); Ai[t] = mul2(K, Ai[t]); }
}

// (-i)^k rotation
__device__ __forceinline__ void rot_mi(int k, float r, float i, float& orr, float& oi) {
    switch (k & 3) {
        case 0:  orr = r;  oi = i;  break;
        case 1:  orr = i;  oi = -r; break;
        case 2:  orr = -r; oi = -i; break;
        default: orr = -i; oi = r;  break;
    }
}

// one component of  Rz(wa)Rz(wb) * XX(phi) * (Rx|0> (x) Rx|0>)  on a wire pair
__device__ void pair_component(const float* p, const float* cp, int b,
                               int wa, int wb, int xxidx, int sel,
                               float& outr, float& outi) {
    float ca, sa, cbw, sbw, cx, sx;
    sincosf(0.5f * p[b * 42 + wa], &sa, &ca);
    sincosf(0.5f * p[b * 42 + wb], &sbw, &cbw);
    sincosf(0.5f * cp[b * 14 + xxidx], &sx, &cx);
    float vr[4] = {ca * cbw, 0.0f, 0.0f, -sa * sbw};
    float vi[4] = {0.0f, -ca * sbw, -sa * cbw, 0.0f};
    float nr[4], ni[4];
    nr[0] = cx * vr[0] + sx * vi[3]; ni[0] = cx * vi[0] - sx * vr[3];
    nr[3] = cx * vr[3] + sx * vi[0]; ni[3] = cx * vi[3] - sx * vr[0];
    nr[1] = cx * vr[1] + sx * vi[2]; ni[1] = cx * vi[1] - sx * vr[2];
    nr[2] = cx * vr[2] + sx * vi[1]; ni[2] = cx * vi[2] - sx * vr[1];
    float tha = p[b * 42 + 14 + wa], thb = p[b * 42 + 14 + wb];
    float ph = 0.5f * (((sel >> 1) ? tha : -tha) + ((sel & 1) ? thb : -thb));
    float cph, sph; sincosf(ph, &sph, &cph);
    float ur = nr[sel], ui = ni[sel];
    outr = ur * cph - ui * sph;
    outi = ui * cph + ur * sph;
}

// ---------------- main kernel ------------------------------------------------
__global__ void __launch_bounds__(NTH, 1)
quantum_kernel(const float* __restrict__ cp, const float* __restrict__ p,
               float* __restrict__ out) {
    extern __shared__ float sm[];
    float* RE = sm;
    float* IM = sm + PAD_SLOTS;

    __shared__ float c1[NQ], s1[NQ];
    __shared__ float txv[NQ];          // tan(xx half): [0..6]=a, [7..13]=b
    __shared__ float t3[NQ];           // tan(rx3 half)
    __shared__ float tz[NQ];           // tan(rz half)
    __shared__ float cxc[NQ], c3c[NQ], czc[NQ];
    __shared__ float Vhr[16], Vhi2[16];  // raw wires 0-3 table
    __shared__ float Whr[16], Whi[16];   // folded (+XXb(1,2), Rx3(1,2))
    __shared__ float chi_r[4], chi_i[4];
    __shared__ float kapA[3];
    __shared__ float red[16][11];
    __shared__ int sm_b;

    const int tid = threadIdx.x;

    // prologue: fetch first batch id
    if (tid == 0) sm_b = atomicAdd(&d_ctr, 1);
    __syncthreads();

    for (;;) {
        const int b = sm_b;
        if (b >= BATCH) break;

        // ---------------- setup stage 1 ----------------
        if (tid < 16) {
            float w1r, w1i, w2r, w2i;
            pair_component(p, cp, b, 0, 1, 0, tid >> 2, w1r, w1i);
            pair_component(p, cp, b, 2, 3, 1, tid & 3,  w2r, w2i);
            Vhr[tid]  = w1r * w2r - w1i * w2i;
            Vhi2[tid] = w1r * w2i + w1i * w2r;
        }
        if (tid >= 16 && tid < 20) {
            float cr_, ci_;
            pair_component(p, cp, b, 12, 13, 6, tid - 16, cr_, ci_);
            chi_r[tid - 16] = cr_; chi_i[tid - 16] = ci_;
        }
        if (tid >= 32 && tid < 32 + NQ) {
            int w = tid - 32;
            float c, s; sincosf(0.5f * cp[b * NQ + w], &s, &c);
            txv[w] = __fdividef(s, c); cxc[w] = c;
        }
        if (tid >= 64 && tid < 64 + NQ) {
            int w = tid - 64;
            float c, s; sincosf(0.5f * p[b * 42 + 28 + w], &s, &c);
            t3[w] = __fdividef(s, c); c3c[w] = c;
        }
        if (tid >= 96 && tid < 96 + NQ) {
            int w = tid - 96;
            float c, s; sincosf(0.5f * p[b * 42 + 14 + w], &s, &c);
            tz[w] = __fdividef(s, c); czc[w] = c;
        }
        if (tid >= 128 && tid < 128 + NQ) {
            int w = tid - 128;
            sincosf(0.5f * p[b * 42 + w], &s1[w], &c1[w]);
        }
        __syncthreads();   // S1

        // ---------------- setup stage 2 (parallel fold + kappas) ------------
        if (tid < 32) {
            // warp-0 shuffle fold of XXb(1,2), Rx3(1), Rx3(2) into W (exact)
            float fvr = Vhr[tid & 15], fvi = Vhi2[tid & 15];
            float cx, sx, pr_, pi_, nr_, ni_;
            sincosf(0.5f * cp[b * NQ + 7], &sx, &cx);        // XXb(1,2): mask 6
            pr_ = __shfl_xor_sync(0xffffffffu, fvr, 6);
            pi_ = __shfl_xor_sync(0xffffffffu, fvi, 6);
            nr_ = cx * fvr + sx * pi_; ni_ = cx * fvi - sx * pr_;
            fvr = nr_; fvi = ni_;
            sincosf(0.5f * p[b * 42 + 28 + 1], &sx, &cx);    // Rx3(1): mask 4
            pr_ = __shfl_xor_sync(0xffffffffu, fvr, 4);
            pi_ = __shfl_xor_sync(0xffffffffu, fvi, 4);
            nr_ = cx * fvr + sx * pi_; ni_ = cx * fvi - sx * pr_;
            fvr = nr_; fvi = ni_;
            sincosf(0.5f * p[b * 42 + 28 + 2], &sx, &cx);    // Rx3(2): mask 2
            pr_ = __shfl_xor_sync(0xffffffffu, fvr, 2);
            pi_ = __shfl_xor_sync(0xffffffffu, fvi, 2);
            nr_ = cx * fvr + sx * pi_; ni_ = cx * fvi - sx * pr_;
            fvr = nr_; fvi = ni_;
            if (tid < 16) { Whr[tid] = fvr; Whi[tid] = fvi; }
        }
        else if (tid == 32)   // phase A cosines (from tables; own warp)
            kapA[0] = cxc[2] * cxc[3] * czc[4] * czc[5] * czc[6] * czc[7] *
                      cxc[8] * cxc[9] * c3c[3] * c3c[4] * c3c[5] * c3c[6];
        else if (tid == 64)   // phase B cosines
            kapA[1] = cxc[4] * cxc[5] * czc[8] * czc[9] * czc[10] * czc[11] *
                      cxc[10] * cxc[11] * c3c[7] * c3c[8] * c3c[9] * c3c[10];
        else if (tid == 96)   // phase C cosines
            kapA[2] = cxc[12] * cxc[13] * c3c[0] * c3c[11] * c3c[12] * c3c[13];
        __syncthreads();   // S2

        u64 Ar[16], Ai[16];

        // ====== PHASE A: resident wires {3,4,5,6,7} = j bits {10,9,8,7,6} ====
        // reg: t3=j10(w3) t2=j9(w4) t1=j8(w5) t0=j7(w6); pack=j6(w7)
        // thread: tid[8:6]=j[13:11] (wires 0,1,2); tid[5:0]=j[5:0] (wires 8-13)
        {
            float Pl = 1.0f;
            Pl *= ((tid >> 5) & 1) ? s1[8]  : c1[8];
            Pl *= ((tid >> 4) & 1) ? s1[9]  : c1[9];
            Pl *= ((tid >> 3) & 1) ? s1[10] : c1[10];
            Pl *= ((tid >> 2) & 1) ? s1[11] : c1[11];
            int pcl = __popc(tid & 0x3C);
            float Cr = chi_r[tid & 3], Ci = chi_i[tid & 3];
            float Br, Bi; rot_mi(pcl, Cr, Ci, Br, Bi);
            Br *= Pl; Bi *= Pl;
            int vb = ((tid >> 8) & 1) * 8 + ((tid >> 7) & 1) * 4 + ((tid >> 6) & 1) * 2;
            float X0r = Whr[vb]     * Br - Whi[vb]     * Bi;
            float X0i = Whr[vb]     * Bi + Whi[vb]     * Br;
            float X1r = Whr[vb | 1] * Br - Whi[vb | 1] * Bi;
            float X1i = Whr[vb | 1] * Bi + Whi[vb | 1] * Br;
            float c7 = c1[7], s7 = s1[7];
#pragma unroll
            for (int t = 0; t < 16; t++) {
                float f = 1.0f;
                f *= (t & 4) ? s1[4] : c1[4];
                f *= (t & 2) ? s1[5] : c1[5];
                f *= (t & 1) ? s1[6] : c1[6];
                float xr, xi;
                rot_mi(__popc(t & 7), (t & 8) ? X1r : X0r, (t & 8) ? X1i : X0i,
                       xr, xi);
                Ar[t] = pk2(xr * f * c7,  xi * f * s7);
                Ai[t] = pk2(xi * f * c7, -xr * f * s7);
            }
        }
        { Gf g = mkgf(txv[2]); xxf<4, 2>(Ar, Ai, g); }   // XXa(4,5)
        xxpf<1>(Ar, Ai, txv[3]);                         // XXa(6,7) pack x t0
        { Gf g = mkgf(tz[4]); rzf<4>(Ar, Ai, g); }
        { Gf g = mkgf(tz[5]); rzf<2>(Ar, Ai, g); }
        { Gf g = mkgf(tz[6]); rzf<1>(Ar, Ai, g); }
        rzpf(Ar, Ai, tz[7]);                             // Rz(7) on pack
        { Gf g = mkgf(txv[8]); xxf<8, 4>(Ar, Ai, g); }   // XXb(3,4)
        { Gf g = mkgf(txv[9]); xxf<2, 1>(Ar, Ai, g); }   // XXb(5,6)
        { Gf g = mkgf(t3[3]); rxf<8>(Ar, Ai, g); }
        { Gf g = mkgf(t3[4]); rxf<4>(Ar, Ai, g); }
        { Gf g = mkgf(t3[5]); rxf<2>(Ar, Ai, g); }
        { Gf g = mkgf(t3[6]); rxf<1>(Ar, Ai, g); }
        scale32(Ar, Ai, kapA[0]);
        {
            int a = ((tid >> 8) & 1) * 8448 + ((tid >> 7) & 1) * 4224
                  + ((tid >> 6) & 1) * 2112 + ((tid >> 5) & 1) * 33 + (tid & 31);
#pragma unroll
            for (int t = 0; t < 16; t++) {
                int o = a + ((t >> 3) & 1) * 1056 + ((t >> 2) & 1) * 528
                          + ((t >> 1) & 1) * 264  + (t & 1) * 132;
                float lo, hi;
                up2(Ar[t], lo, hi); RE[o] = lo; RE[o + 66] = hi;
                up2(Ai[t], lo, hi); IM[o] = lo; IM[o + 66] = hi;
            }
        }
        __syncthreads();   // S3

        // ====== PHASE B: resident wires {7,8,9,10,11} = j bits {6,5,4,3,2} ===
        {
            int a = (tid & 1) + ((tid >> 1) & 1) * 2 + ((tid >> 2) & 1) * 132
                  + ((tid >> 3) & 1) * 264 + ((tid >> 4) & 1) * 528
                  + ((tid >> 5) & 1) * 1056 + ((tid >> 6) & 1) * 2112
                  + ((tid >> 7) & 1) * 4224 + ((tid >> 8) & 1) * 8448;
#pragma unroll
            for (int t = 0; t < 16; t++) {
                int o = a + ((t >> 3) & 1) * 66 + ((t >> 2) & 1) * 33
                          + ((t >> 1) & 1) * 16 + (t & 1) * 8;
                Ar[t] = pk2(RE[o], RE[o + 4]);
                Ai[t] = pk2(IM[o], IM[o + 4]);
            }
            // prefetch next batch id (hidden behind the other 15 warps' gates;
            // visibility to all threads guaranteed by S4)
            if (tid == 0) sm_b = atomicAdd(&d_ctr, 1);

            { Gf g = mkgf(txv[4]); xxf<4, 2>(Ar, Ai, g); }   // XXa(8,9)
            xxpf<1>(Ar, Ai, txv[5]);                         // XXa(10,11) pack x t0
            { Gf g = mkgf(tz[8]);  rzf<4>(Ar, Ai, g); }
            { Gf g = mkgf(tz[9]);  rzf<2>(Ar, Ai, g); }
            { Gf g = mkgf(tz[10]); rzf<1>(Ar, Ai, g); }
            rzpf(Ar, Ai, tz[11]);                            // Rz(11) on pack
            { Gf g = mkgf(txv[10]); xxf<8, 4>(Ar, Ai, g); }  // XXb(7,8)
            { Gf g = mkgf(txv[11]); xxf<2, 1>(Ar, Ai, g); }  // XXb(9,10)
            { Gf g = mkgf(t3[7]);  rxf<8>(Ar, Ai, g); }
            { Gf g = mkgf(t3[8]);  rxf<4>(Ar, Ai, g); }
            { Gf g = mkgf(t3[9]);  rxf<2>(Ar, Ai, g); }
            { Gf g = mkgf(t3[10]); rxf<1>(Ar, Ai, g); }
            scale32(Ar, Ai, kapA[1]);
#pragma unroll
            for (int t = 0; t < 16; t++) {
                int o = a + ((t >> 3) & 1) * 66 + ((t >> 2) & 1) * 33
                          + ((t >> 1) & 1) * 16 + (t & 1) * 8;
                float lo, hi;
                up2(Ar[t], lo, hi); RE[o] = lo; RE[o + 4] = hi;
                up2(Ai[t], lo, hi); IM[o] = lo; IM[o + 4] = hi;
            }
        }
        __syncthreads();   // S4

        // ====== PHASE C: resident wires {0,11,12,13}+w10 = j {13,2,1,0}+j3 ===
        float k5;
        {
            k5 = kapA[2];   // stash (next batch's kappa write is gated by S2)
            int a = (tid & 1) * 16 + ((tid >> 1) & 1) * 33 + ((tid >> 2) & 1) * 66
                  + ((tid >> 3) & 1) * 132 + ((tid >> 4) & 1) * 264
                  + ((tid >> 5) & 1) * 528 + ((tid >> 6) & 1) * 1056
                  + ((tid >> 7) & 1) * 2112 + ((tid >> 8) & 1) * 4224;
#pragma unroll
            for (int t = 0; t < 16; t++) {
                int o = a + ((t >> 3) & 1) * 8448 + ((t >> 2) & 1) * 4
                          + ((t >> 1) & 1) * 2 + (t & 1);
                Ar[t] = pk2(RE[o], RE[o + 8]);
                Ai[t] = pk2(IM[o], IM[o + 8]);
            }
            { Gf g = mkgf(txv[12]); xxf<4, 2>(Ar, Ai, g); }  // XXb(11,12)
            { Gf g = mkgf(txv[13]); xxf<1, 8>(Ar, Ai, g); }  // XXb(13,0)
            { Gf g = mkgf(t3[0]);   rxf<8>(Ar, Ai, g); }
            { Gf g = mkgf(t3[11]);  rxf<4>(Ar, Ai, g); }
            { Gf g = mkgf(t3[12]);  rxf<2>(Ar, Ai, g); }
            { Gf g = mkgf(t3[13]);  rxf<1>(Ar, Ai, g); }

            // scaled probabilities -> smem (true prob = k5^2 * value)
#pragma unroll
            for (int t = 0; t < 16; t++) {
                int o = a + ((t >> 3) & 1) * 8448 + ((t >> 2) & 1) * 4
                          + ((t >> 1) & 1) * 2 + (t & 1);
                u64 Pr = fma2(Ai[t], Ai[t], mul2(Ar[t], Ar[t]));
                float lo, hi; up2(Pr, lo, hi);
                RE[o] = lo; RE[o + 8] = hi;
            }
        }
        __syncthreads();   // S5

        // ====== epilogue: inverse-permuted gather + Walsh trees ==============
        float l1[16], a4 = 0.0f;
#pragma unroll
        for (int k = 0; k < 16; k++) {
            int y0 = (k << 10) | tid;
            int y1 = y0 | 512;
            float v0 = RE[d_permtab[y0]];     // table stores padded slot
            float v1 = RE[d_permtab[y1]];
            l1[k] = v0 + v1;
            a4 += v0 - v1;
        }
        float l2[8], a3 = 0.0f;
#pragma unroll
        for (int k = 0; k < 8; k++) { l2[k] = l1[2*k] + l1[2*k+1]; a3 += l1[2*k] - l1[2*k+1]; }
        float l3[4], a2 = 0.0f;
#pragma unroll
        for (int k = 0; k < 4; k++) { l3[k] = l2[2*k] + l2[2*k+1]; a2 += l2[2*k] - l2[2*k+1]; }
        float l4[2], a1 = 0.0f;
#pragma unroll
        for (int k = 0; k < 2; k++) { l4[k] = l3[2*k] + l3[2*k+1]; a1 += l3[2*k] - l3[2*k+1]; }
        float T  = l4[0] + l4[1];
        float a0 = l4[0] - l4[1];

        // warp butterfly over lane bits 0..4 (tid bits <-> wires 13..9)
        float av[5] = {a0, a1, a2, a3, a4};
        float d[5];
#pragma unroll
        for (int k = 0; k < 5; k++) {
            float pT = __shfl_xor_sync(0xffffffffu, T, 1 << k);
            d[k] = T - pT;
            T += pT;
#pragma unroll
            for (int j = 0; j < 5; j++)
                av[j] += __shfl_xor_sync(0xffffffffu, av[j], 1 << k);
#pragma unroll
            for (int m = 0; m < 5; m++)
                if (m < k) d[m] += __shfl_xor_sync(0xffffffffu, d[m], 1 << k);
        }
        if ((tid & 31) == 0) {
            int wp = tid >> 5;
#pragma unroll
            for (int j = 0; j < 5; j++) red[wp][j] = av[j];
#pragma unroll
            for (int k = 0; k < 5; k++) red[wp][5 + k] = d[k];
            red[wp][10] = T;
        }
        __syncthreads();   // S6

        // parallel tail: warp w reduces wire w over the 16 partials
        if (tid < NQ * 32) {
            int w = tid >> 5;
            int r = tid & 31;
            float v = 0.0f;
            if (r < 16) {
                if (w < 5) {
                    v = red[r][w];                        // wires 0-4
                } else if (w < 9) {
                    float Tt = red[r][10];                // wires 5-8
                    v = ((r >> (8 - w)) & 1) ? -Tt : Tt;
                } else {
                    v = red[r][5 + (13 - w)];             // wires 9-13
                }
            }
#pragma unroll
            for (int o = 8; o; o >>= 1) v += __shfl_xor_sync(0xffffffffu, v, o);
            if (r == 0)
                out[b * NQ + w] = (v * k5) * k5;
        }
        // no loop-top barrier: next-iteration table writes are gated by S1/S2,
        // which tail warps must also reach; tail reads only red[] and k5 (reg).
    }
}

extern "C" void kernel_launch(void* const* d_in, const int* in_sizes, int n_in,
                              void* d_out, int out_size) {
    const float* cp = (const float*)d_in[0];   // (512, 14)
    const float* p  = (const float*)d_in[1];   // (512, 3, 14)
    float* out      = (float*)d_out;           // (512, 14)

    build_perm_kernel<<<NS / 1024, 1024>>>();

    size_t smem = (size_t)PAD_SLOTS * 2 * sizeof(float);  // 135168 bytes
    cudaFuncSetAttribute(quantum_kernel,
                         cudaFuncAttributeMaxDynamicSharedMemorySize, (int)smem);
    quantum_kernel<<<GRID, NTH, smem>>>(cp, p, out);
}